// round 3
// baseline (speedup 1.0000x reference)
#include <cuda_runtime.h>
#include <math.h>

#define BB 4
#define NN 4096
#define NFF 8192
#define KK 512
#define CC 128
#define LL 4
#define INDIM 3
#define FCD 128

// -------- scratch (device globals; no dynamic allocation allowed) --------
__device__ float g_Bc[BB*KK*NN];     // cos basis at ind points   (32 MB)
__device__ float g_Bs[BB*KK*NN];     // sin basis                 (32 MB)
__device__ float g_wqn[BB*NN];       // wq * N at ind points
__device__ float g_h[2][BB*CC*NN];   // ping-pong hidden state
__device__ float g_hw[BB*CC*NN];     // h0 * wqn  (loop-invariant!)
__device__ float g_xch[BB*CC*KK];    // forward cos coeffs (from h0, once)
__device__ float g_xsp[BB*CC*KK];    // forward +sin coeffs (xsh = -xsp)
__device__ float g_fA[BB*CC*KK];     //  2*fch/nf
__device__ float g_fB[BB*CC*KK];     // -2*fsh/nf
__device__ float g_x0h[BB*CC];
__device__ float g_f0h[BB*CC];       // f0h/nf + conv_b

__device__ __forceinline__ float gelu_exact(float v) {
    return 0.5f * v * (1.0f + erff(v * 0.7071067811865476f));
}

// -------- K1: basis precompute --------
__global__ void k_basis(const float* __restrict__ xf, const int* __restrict__ ind,
                        const float* __restrict__ modes) {
    int idx = blockIdx.x * blockDim.x + threadIdx.x;
    if (idx >= BB*KK*NN) return;
    int n = idx & (NN - 1);
    int k = (idx >> 12) & (KK - 1);
    int b = idx >> 21;
    int f = __ldg(&ind[n]);
    const float* xfp = xf + ((size_t)b * NFF + f) * 4;
    float gx = __ldg(&xfp[0]);
    float gy = __ldg(&xfp[1]);
    float wq = __ldg(&xfp[2]);
    float mx = __ldg(&modes[2*k]);
    float my = __ldg(&modes[2*k+1]);
    float t = gx * mx + gy * my;
    float s, c;
    sincosf(t, &s, &c);
    g_Bc[idx] = c;
    g_Bs[idx] = s;
    if (k == 0) g_wqn[b*NN + n] = wq * (float)NN;
}

// -------- K2: fc0  h[b,c,n] = x[b,n,:3] @ fc0_w[:,c] + b --------
__global__ void k_fc0(const float* __restrict__ x, const float* __restrict__ w,
                      const float* __restrict__ bias) {
    int n = blockIdx.x * blockDim.x + threadIdx.x;
    int c = blockIdx.y;
    int b = blockIdx.z;
    const float* xp = x + ((size_t)b * NN + n) * INDIM;
    float acc = bias[c]
              + xp[0] * w[0*CC + c]
              + xp[1] * w[1*CC + c]
              + xp[2] * w[2*CC + c];
    size_t o = ((size_t)b*CC + c) * NN + n;
    g_h[0][o] = acc;
    g_hw[o]   = acc * g_wqn[b*NN + n];
}

// -------- K2b: x0h[b,c] = sum_n hw[b,c,n]  (once — xg is loop-invariant) --------
__global__ void k_x0h() {
    int bc = blockIdx.x;  // b*CC + c
    const float* p = g_hw + (size_t)bc * NN;
    float acc = 0.f;
    for (int n = threadIdx.x; n < NN; n += 256) acc += p[n];
    __shared__ float red[256];
    red[threadIdx.x] = acc;
    __syncthreads();
    for (int s = 128; s > 0; s >>= 1) {
        if (threadIdx.x < s) red[threadIdx.x] += red[threadIdx.x + s];
        __syncthreads();
    }
    if (threadIdx.x == 0) g_x0h[bc] = red[0];
}

// -------- K3: forward dual GEMM (once)  xch/xsp[b,c,k] = sum_n hw*Bc/Bs --------
__global__ void k_fwd() {
    __shared__ float sA[32][33];
    __shared__ float sBc[32][33];
    __shared__ float sBs[32][33];
    int b  = blockIdx.z;
    int m0 = blockIdx.y * 32;
    int k0 = blockIdx.x * 32;
    int tid = threadIdx.x;
    int tx = tid & 15, ty = tid >> 4;
    float ac[2][2] = {{0.f,0.f},{0.f,0.f}};
    float as_[2][2] = {{0.f,0.f},{0.f,0.f}};
    const float* A  = g_hw + ((size_t)b*CC + m0) * NN;
    const float* Bc = g_Bc + ((size_t)b*KK + k0) * NN;
    const float* Bs = g_Bs + ((size_t)b*KK + k0) * NN;
    int lr = tid & 31;
    int lm = tid >> 5;  // 0..7
    for (int r0 = 0; r0 < NN; r0 += 32) {
        #pragma unroll
        for (int i = 0; i < 4; i++) {
            int m = lm + 8*i;
            sA[lr][m]  = A [(size_t)m*NN + r0 + lr];
            sBc[lr][m] = Bc[(size_t)m*NN + r0 + lr];
            sBs[lr][m] = Bs[(size_t)m*NN + r0 + lr];
        }
        __syncthreads();
        #pragma unroll 8
        for (int r = 0; r < 32; r++) {
            float a0 = sA[r][ty],  a1 = sA[r][ty+16];
            float c0 = sBc[r][tx], c1 = sBc[r][tx+16];
            float s0 = sBs[r][tx], s1 = sBs[r][tx+16];
            ac[0][0]  += a0*c0; ac[0][1]  += a0*c1;
            ac[1][0]  += a1*c0; ac[1][1]  += a1*c1;
            as_[0][0] += a0*s0; as_[0][1] += a0*s1;
            as_[1][0] += a1*s0; as_[1][1] += a1*s1;
        }
        __syncthreads();
    }
    #pragma unroll
    for (int i = 0; i < 2; i++)
        #pragma unroll
        for (int j = 0; j < 2; j++) {
            int m = m0 + ty + 16*i;
            int k = k0 + tx + 16*j;
            g_xch[((size_t)b*CC + m)*KK + k] = ac[i][j];
            g_xsp[((size_t)b*CC + m)*KK + k] = as_[i][j];
        }
}

// -------- K4: mode mix; streams wc/ws with k coalesced --------
__global__ void k_mix(const float* __restrict__ wc, const float* __restrict__ ws, int l) {
    int o = blockIdx.x;      // 0..127
    int k = threadIdx.x;     // 0..511
    const float inv_nf = 1.0f / (float)NFF;
    float accc[BB] = {0.f,0.f,0.f,0.f};
    float accs[BB] = {0.f,0.f,0.f,0.f};
    const float* wcp = wc + (((size_t)l*CC)*CC + o)*KK + k;
    const float* wsp = ws + (((size_t)l*CC)*CC + o)*KK + k;
    #pragma unroll 2
    for (int i = 0; i < CC; i++) {
        float wcv = __ldg(&wcp[(size_t)i*CC*KK]);
        float wsv = __ldg(&wsp[(size_t)i*CC*KK]);
        #pragma unroll
        for (int b = 0; b < BB; b++) {
            float xc = g_xch[((size_t)b*CC + i)*KK + k];
            float xs = g_xsp[((size_t)b*CC + i)*KK + k];
            accc[b] += xc*wcv + xs*wsv;
            accs[b] += xc*wsv - xs*wcv;
        }
    }
    #pragma unroll
    for (int b = 0; b < BB; b++) {
        g_fA[((size_t)b*CC + o)*KK + k] =  2.0f * inv_nf * accc[b];
        g_fB[((size_t)b*CC + o)*KK + k] = -2.0f * inv_nf * accs[b];
    }
}

// -------- K4b: f0h[b,o] = (sum_i x0h[b,i]*w0[l,i,o])/nf + conv_b[l,o] --------
__global__ void k_f0h(const float* __restrict__ w0, const float* __restrict__ convb, int l) {
    int t = threadIdx.x;   // 0..511
    int b = t >> 7, o = t & 127;
    float acc = 0.f;
    #pragma unroll 4
    for (int i = 0; i < CC; i++)
        acc += g_x0h[b*CC + i] * __ldg(&w0[((size_t)l*CC + i)*CC + o]);
    g_f0h[t] = acc * (1.0f / (float)NFF) + convb[l*CC + o];
}

// -------- K5: fused inverse + conv + bias + gelu --------
__global__ void k_inv(const float* __restrict__ convw, int l, int cur) {
    __shared__ float sA1[16][65];
    __shared__ float sA2[16][65];
    __shared__ float sB1[16][64];
    __shared__ float sB2[16][64];
    int b  = blockIdx.z;
    int m0 = blockIdx.y * 64;
    int n0 = blockIdx.x * 64;
    int tid = threadIdx.x;
    int tx = tid & 15, ty = tid >> 4;
    float acc[4][4] = {};
    int alr = tid & 15, alm = tid >> 4;   // A loader
    int blr = tid >> 6, bln = tid & 63;   // B loader
    const float* fA  = g_fA + ((size_t)b*CC + m0) * KK;
    const float* fBm = g_fB + ((size_t)b*CC + m0) * KK;
    const float* Bc  = g_Bc + (size_t)b*KK*NN;
    const float* Bs  = g_Bs + (size_t)b*KK*NN;
    // ---- spectral phase: reduce over K=512, two matrix pairs ----
    for (int r0 = 0; r0 < KK; r0 += 16) {
        #pragma unroll
        for (int i = 0; i < 4; i++) {
            int m = alm + 16*i;
            sA1[alr][m] = fA [(size_t)m*KK + r0 + alr];
            sA2[alr][m] = fBm[(size_t)m*KK + r0 + alr];
        }
        #pragma unroll
        for (int i = 0; i < 4; i++) {
            int r = blr + 4*i;
            sB1[r][bln] = Bc[(size_t)(r0 + r)*NN + n0 + bln];
            sB2[r][bln] = Bs[(size_t)(r0 + r)*NN + n0 + bln];
        }
        __syncthreads();
        #pragma unroll
        for (int r = 0; r < 16; r++) {
            float a1[4], a2[4], b1[4], b2[4];
            #pragma unroll
            for (int i = 0; i < 4; i++) { a1[i] = sA1[r][ty+16*i]; a2[i] = sA2[r][ty+16*i]; }
            #pragma unroll
            for (int j = 0; j < 4; j++) { b1[j] = sB1[r][tx+16*j]; b2[j] = sB2[r][tx+16*j]; }
            #pragma unroll
            for (int i = 0; i < 4; i++)
                #pragma unroll
                for (int j = 0; j < 4; j++)
                    acc[i][j] += a1[i]*b1[j] + a2[i]*b2[j];
        }
        __syncthreads();
    }
    // ---- conv phase: reduce over C=128 ----
    const float* Wv = convw + (size_t)l*CC*CC + (size_t)m0*CC;
    const float* H  = g_h[cur] + (size_t)b*CC*NN;
    for (int r0 = 0; r0 < CC; r0 += 16) {
        #pragma unroll
        for (int i = 0; i < 4; i++) {
            int m = alm + 16*i;
            sA1[alr][m] = Wv[(size_t)m*CC + r0 + alr];
        }
        #pragma unroll
        for (int i = 0; i < 4; i++) {
            int r = blr + 4*i;
            sB1[r][bln] = H[(size_t)(r0 + r)*NN + n0 + bln];
        }
        __syncthreads();
        #pragma unroll
        for (int r = 0; r < 16; r++) {
            float a1[4], b1[4];
            #pragma unroll
            for (int i = 0; i < 4; i++) a1[i] = sA1[r][ty+16*i];
            #pragma unroll
            for (int j = 0; j < 4; j++) b1[j] = sB1[r][tx+16*j];
            #pragma unroll
            for (int i = 0; i < 4; i++)
                #pragma unroll
                for (int j = 0; j < 4; j++)
                    acc[i][j] += a1[i]*b1[j];
        }
        __syncthreads();
    }
    // ---- epilogue ----
    int nxt = cur ^ 1;
    #pragma unroll
    for (int i = 0; i < 4; i++) {
        int m = m0 + ty + 16*i;
        float bias = g_f0h[b*CC + m];
        #pragma unroll
        for (int j = 0; j < 4; j++) {
            int n = n0 + tx + 16*j;
            float v = acc[i][j] + bias;
            if (l < LL - 1) v = gelu_exact(v);
            g_h[nxt][((size_t)b*CC + m)*NN + n] = v;
        }
    }
}

// -------- K6: head  out[b,n] = gelu(h^T fc1 + b1) fc2 + b2 --------
__global__ void k_head(const float* __restrict__ w1, const float* __restrict__ b1,
                       const float* __restrict__ w2, const float* __restrict__ b2,
                       float* __restrict__ out, int cur) {
    __shared__ float sh[CC][32];
    __shared__ float red[CC][33];
    int b  = blockIdx.y;
    int n0 = blockIdx.x * 32;
    int f = threadIdx.x;  // 0..127
    const float* H = g_h[cur] + (size_t)b*CC*NN + n0;
    #pragma unroll 4
    for (int c4 = 0; c4 < CC; c4 += 4) {
        int row = c4 + (f >> 5);
        int col = f & 31;
        sh[row][col] = H[(size_t)row*NN + col];
    }
    __syncthreads();
    float acc[32];
    float bv = b1[f];
    #pragma unroll
    for (int j = 0; j < 32; j++) acc[j] = bv;
    for (int c = 0; c < CC; c++) {
        float w = __ldg(&w1[(size_t)c*FCD + f]);
        #pragma unroll
        for (int j = 0; j < 32; j++) acc[j] += sh[c][j] * w;
    }
    float w2f = __ldg(&w2[f]);
    #pragma unroll
    for (int j = 0; j < 32; j++)
        red[f][j] = gelu_exact(acc[j]) * w2f;
    __syncthreads();
    if (f < 32) {
        float s = b2[0];
        #pragma unroll 8
        for (int q = 0; q < CC; q++) s += red[q][f];
        out[(size_t)b*NN + n0 + f] = s;
    }
}

// -------- launch --------
extern "C" void kernel_launch(void* const* d_in, const int* in_sizes, int n_in,
                              void* d_out, int out_size) {
    (void)in_sizes; (void)n_in; (void)out_size;
    const float* x     = (const float*)d_in[0];
    const float* xf    = (const float*)d_in[1];
    const int*   ind   = (const int*)  d_in[2];
    const float* modes = (const float*)d_in[3];
    const float* fc0_w = (const float*)d_in[4];
    const float* fc0_b = (const float*)d_in[5];
    const float* wc    = (const float*)d_in[6];
    const float* ws    = (const float*)d_in[7];
    const float* w0    = (const float*)d_in[8];
    const float* convw = (const float*)d_in[9];
    const float* convb = (const float*)d_in[10];
    const float* fc1_w = (const float*)d_in[11];
    const float* fc1_b = (const float*)d_in[12];
    const float* fc2_w = (const float*)d_in[13];
    const float* fc2_b = (const float*)d_in[14];
    float* out = (float*)d_out;

    k_basis<<<(BB*KK*NN + 255)/256, 256>>>(xf, ind, modes);

    dim3 g2(NN/256, CC, BB);
    k_fc0<<<g2, 256>>>(x, fc0_w, fc0_b);

    // Forward spectral transform is LOOP-INVARIANT (reference never updates xg):
    // compute once from h0.
    k_x0h<<<BB*CC, 256>>>();
    dim3 g3(KK/32, CC/32, BB);
    k_fwd<<<g3, 256>>>();

    int cur = 0;
    for (int l = 0; l < LL; l++) {
        k_mix<<<CC, KK>>>(wc, ws, l);
        k_f0h<<<1, BB*CC>>>(w0, convb, l);
        dim3 g5(NN/64, CC/64, BB);
        k_inv<<<g5, 256>>>(convw, l, cur);
        cur ^= 1;
    }

    dim3 g6(NN/32, BB);
    k_head<<<g6, 128>>>(fc1_w, fc1_b, fc2_w, fc2_b, out, cur);
}

// round 4
// speedup vs baseline: 1.7507x; 1.7507x over previous
#include <cuda_runtime.h>
#include <math.h>
#include <stdint.h>

#define BB 4
#define NN 4096
#define NFF 8192
#define KK 512
#define CC 128
#define LL 4
#define INDIM 3
#define FCD 128

// -------- scratch (device globals) --------
__device__ float g_Bc[BB*KK*NN];     // cos basis (32 MB)
__device__ float g_Bs[BB*KK*NN];     // sin basis (32 MB)
__device__ float g_wqn[BB*NN];
__device__ float g_h[2][BB*CC*NN];   // ping-pong hidden state
__device__ float g_hw[BB*CC*NN];     // pre-loop: h0*wqn; in-loop: x1 spectral partial
__device__ float g_xch[BB*CC*KK];
__device__ float g_xsp[BB*CC*KK];
__device__ float g_fA[BB*CC*KK];     //  2*fch/nf
__device__ float g_fB[BB*CC*KK];     // -2*fsh/nf
__device__ float g_x0h[BB*CC];
__device__ float g_f0h[BB*CC];

__device__ __forceinline__ float gelu_exact(float v) {
    return 0.5f * v * (1.0f + erff(v * 0.7071067811865476f));
}

// tf32 mma: D(16x8) += A(16x8) * B(8x8), fp32 accum
__device__ __forceinline__ void mma_tf32(float (&d)[4], const uint32_t (&a)[4],
                                         const uint32_t (&b)[2]) {
    asm volatile(
        "mma.sync.aligned.m16n8k8.row.col.f32.tf32.tf32.f32 "
        "{%0,%1,%2,%3}, {%4,%5,%6,%7}, {%8,%9}, {%0,%1,%2,%3};"
        : "+f"(d[0]), "+f"(d[1]), "+f"(d[2]), "+f"(d[3])
        : "r"(a[0]), "r"(a[1]), "r"(a[2]), "r"(a[3]), "r"(b[0]), "r"(b[1]));
}

// -------- K1: basis precompute (fast sincos — error ~1e-5 abs on tiny path) --------
__global__ void k_basis(const float* __restrict__ xf, const int* __restrict__ ind,
                        const float* __restrict__ modes) {
    int idx = blockIdx.x * blockDim.x + threadIdx.x;
    if (idx >= BB*KK*NN) return;
    int n = idx & (NN - 1);
    int k = (idx >> 12) & (KK - 1);
    int b = idx >> 21;
    int f = __ldg(&ind[n]);
    const float* xfp = xf + ((size_t)b * NFF + f) * 4;
    float gx = __ldg(&xfp[0]);
    float gy = __ldg(&xfp[1]);
    float wq = __ldg(&xfp[2]);
    float mx = __ldg(&modes[2*k]);
    float my = __ldg(&modes[2*k+1]);
    float t = gx * mx + gy * my;
    float s, c;
    __sincosf(t, &s, &c);
    g_Bc[idx] = c;
    g_Bs[idx] = s;
    if (k == 0) g_wqn[b*NN + n] = wq * (float)NN;
}

// -------- K2: fc0 --------
__global__ void k_fc0(const float* __restrict__ x, const float* __restrict__ w,
                      const float* __restrict__ bias) {
    int n = blockIdx.x * blockDim.x + threadIdx.x;
    int c = blockIdx.y;
    int b = blockIdx.z;
    const float* xp = x + ((size_t)b * NN + n) * INDIM;
    float acc = bias[c]
              + xp[0] * w[0*CC + c]
              + xp[1] * w[1*CC + c]
              + xp[2] * w[2*CC + c];
    size_t o = ((size_t)b*CC + c) * NN + n;
    g_h[0][o] = acc;
    g_hw[o]   = acc * g_wqn[b*NN + n];
}

// -------- K2b: x0h reduce (once) --------
__global__ void k_x0h() {
    int bc = blockIdx.x;
    const float* p = g_hw + (size_t)bc * NN;
    float acc = 0.f;
    for (int n = threadIdx.x; n < NN; n += 256) acc += p[n];
    __shared__ float red[256];
    red[threadIdx.x] = acc;
    __syncthreads();
    for (int s = 128; s > 0; s >>= 1) {
        if (threadIdx.x < s) red[threadIdx.x] += red[threadIdx.x + s];
        __syncthreads();
    }
    if (threadIdx.x == 0) g_x0h[bc] = red[0];
}

// -------- K3: forward dual GEMM, tf32 tensor cores (once) --------
// xch/xsp[b,c,ko] = sum_n hw[b,c,n] * Bc/Bs[b,ko,n]
// block: 32(c=m) x 64(ko=n), reduce NN in chunks of 32. 8 warps (2m x 4n), warp 16x16.
__global__ void k_fwd_tc() {
    __shared__ float As[32][36];
    __shared__ float Bsm[2][64][36];
    int b   = blockIdx.z;
    int m0  = blockIdx.y * 32;
    int ko0 = blockIdx.x * 64;
    int tid = threadIdx.x;
    int lane = tid & 31, wid = tid >> 5;
    int wm = wid >> 2, wn = wid & 3;
    int g = lane >> 2, tig = lane & 3;
    float acc[2][2][4] = {};   // [cos/sin][n-sub][4]
    const float* A  = g_hw + ((size_t)b*CC + m0) * NN;
    const float* Bc = g_Bc + ((size_t)b*KK + ko0) * NN;
    const float* Bs = g_Bs + ((size_t)b*KK + ko0) * NN;
    int arow = tid >> 3, ac4 = (tid & 7) * 4;
    for (int r0 = 0; r0 < NN; r0 += 32) {
        *(float4*)&As[arow][ac4] = *(const float4*)&A[(size_t)arow*NN + r0 + ac4];
        #pragma unroll
        for (int t = 0; t < 2; t++) {
            int idx = tid + t*256;
            int brow = idx >> 3, bc4 = (idx & 7) * 4;
            *(float4*)&Bsm[0][brow][bc4] = *(const float4*)&Bc[(size_t)brow*NN + r0 + bc4];
            *(float4*)&Bsm[1][brow][bc4] = *(const float4*)&Bs[(size_t)brow*NN + r0 + bc4];
        }
        __syncthreads();
        #pragma unroll
        for (int kk = 0; kk < 32; kk += 8) {
            uint32_t af[4];
            int m = wm * 16;
            af[0] = __float_as_uint(As[m+g  ][kk+tig  ]);
            af[1] = __float_as_uint(As[m+g+8][kk+tig  ]);
            af[2] = __float_as_uint(As[m+g  ][kk+tig+4]);
            af[3] = __float_as_uint(As[m+g+8][kk+tig+4]);
            #pragma unroll
            for (int p = 0; p < 2; p++) {
                #pragma unroll
                for (int ns = 0; ns < 2; ns++) {
                    int n = wn * 16 + ns * 8;
                    uint32_t bf[2];
                    bf[0] = __float_as_uint(Bsm[p][n+g][kk+tig  ]);
                    bf[1] = __float_as_uint(Bsm[p][n+g][kk+tig+4]);
                    mma_tf32(acc[p][ns], af, bf);
                }
            }
        }
        __syncthreads();
    }
    #pragma unroll
    for (int ns = 0; ns < 2; ns++) {
        int m = m0 + wm*16 + g;
        int k = ko0 + wn*16 + ns*8 + tig*2;
        size_t o0 = ((size_t)b*CC + m)*KK + k;
        size_t o1 = ((size_t)b*CC + m + 8)*KK + k;
        g_xch[o0]   = acc[0][ns][0];
        g_xch[o0+1] = acc[0][ns][1];
        g_xch[o1]   = acc[0][ns][2];
        g_xch[o1+1] = acc[0][ns][3];
        g_xsp[o0]   = acc[1][ns][0];
        g_xsp[o0+1] = acc[1][ns][1];
        g_xsp[o1]   = acc[1][ns][2];
        g_xsp[o1+1] = acc[1][ns][3];
    }
}

// -------- K4: mode mix (k coalesced, 512 blocks) --------
__global__ void k_mix(const float* __restrict__ wc, const float* __restrict__ ws, int l) {
    int o  = blockIdx.x;                 // 0..127
    int k  = blockIdx.y * 128 + threadIdx.x;
    const float inv_nf = 1.0f / (float)NFF;
    float accc[BB] = {0.f,0.f,0.f,0.f};
    float accs[BB] = {0.f,0.f,0.f,0.f};
    const float* wcp = wc + (((size_t)l*CC)*CC + o)*KK + k;
    const float* wsp = ws + (((size_t)l*CC)*CC + o)*KK + k;
    #pragma unroll 2
    for (int i = 0; i < CC; i++) {
        float wcv = __ldg(&wcp[(size_t)i*CC*KK]);
        float wsv = __ldg(&wsp[(size_t)i*CC*KK]);
        #pragma unroll
        for (int b = 0; b < BB; b++) {
            float xc = g_xch[((size_t)b*CC + i)*KK + k];
            float xs = g_xsp[((size_t)b*CC + i)*KK + k];
            accc[b] += xc*wcv + xs*wsv;
            accs[b] += xc*wsv - xs*wcv;
        }
    }
    #pragma unroll
    for (int b = 0; b < BB; b++) {
        g_fA[((size_t)b*CC + o)*KK + k] =  2.0f * inv_nf * accc[b];
        g_fB[((size_t)b*CC + o)*KK + k] = -2.0f * inv_nf * accs[b];
    }
}

// -------- K4b: f0h --------
__global__ void k_f0h(const float* __restrict__ w0, const float* __restrict__ convb, int l) {
    int t = threadIdx.x;   // 0..511
    int b = t >> 7, o = t & 127;
    float acc = 0.f;
    #pragma unroll 4
    for (int i = 0; i < CC; i++)
        acc += g_x0h[b*CC + i] * __ldg(&w0[((size_t)l*CC + i)*CC + o]);
    g_f0h[t] = acc * (1.0f / (float)NFF) + convb[l*CC + o];
}

// -------- K5a: inverse spectral GEMM, tf32 tensor cores --------
// x1[b,m,n] = sum_k fA[b,m,k]*Bc[b,k,n] + fB[b,m,k]*Bs[b,k,n]  -> g_hw
// block: 64(m) x 128(n), K-chunks of 16. 8 warps (2m x 4n), warp 32x32.
__global__ void k_inv_spec() {
    __shared__ float As[2][64][20];
    __shared__ float Bsm[2][16][132];
    int b  = blockIdx.z;
    int m0 = blockIdx.y * 64;
    int n0 = blockIdx.x * 128;
    int tid = threadIdx.x;
    int lane = tid & 31, wid = tid >> 5;
    int wm = wid >> 2, wn = wid & 3;
    int g = lane >> 2, tig = lane & 3;
    float acc[2][4][4] = {};   // [m-sub][n-sub][4]
    const float* fA = g_fA + ((size_t)b*CC + m0)*KK;
    const float* fB = g_fB + ((size_t)b*CC + m0)*KK;
    const float* Bc = g_Bc + (size_t)b*KK*NN;
    const float* Bs = g_Bs + (size_t)b*KK*NN;
    int arow = tid >> 2, ac4 = (tid & 3) * 4;
    for (int r0 = 0; r0 < KK; r0 += 16) {
        *(float4*)&As[0][arow][ac4] = *(const float4*)&fA[(size_t)arow*KK + r0 + ac4];
        *(float4*)&As[1][arow][ac4] = *(const float4*)&fB[(size_t)arow*KK + r0 + ac4];
        #pragma unroll
        for (int t = 0; t < 2; t++) {
            int idx = tid + t*256;
            int brow = idx >> 5, bc4 = (idx & 31) * 4;
            *(float4*)&Bsm[0][brow][bc4] = *(const float4*)&Bc[(size_t)(r0+brow)*NN + n0 + bc4];
            *(float4*)&Bsm[1][brow][bc4] = *(const float4*)&Bs[(size_t)(r0+brow)*NN + n0 + bc4];
        }
        __syncthreads();
        #pragma unroll
        for (int kk = 0; kk < 16; kk += 8) {
            #pragma unroll
            for (int p = 0; p < 2; p++) {
                uint32_t af[2][4];
                #pragma unroll
                for (int ms = 0; ms < 2; ms++) {
                    int m = wm*32 + ms*16;
                    af[ms][0] = __float_as_uint(As[p][m+g  ][kk+tig  ]);
                    af[ms][1] = __float_as_uint(As[p][m+g+8][kk+tig  ]);
                    af[ms][2] = __float_as_uint(As[p][m+g  ][kk+tig+4]);
                    af[ms][3] = __float_as_uint(As[p][m+g+8][kk+tig+4]);
                }
                #pragma unroll
                for (int ns = 0; ns < 4; ns++) {
                    int n = wn*32 + ns*8;
                    uint32_t bf[2];
                    bf[0] = __float_as_uint(Bsm[p][kk+tig  ][n+g]);
                    bf[1] = __float_as_uint(Bsm[p][kk+tig+4][n+g]);
                    #pragma unroll
                    for (int ms = 0; ms < 2; ms++)
                        mma_tf32(acc[ms][ns], af[ms], bf);
                }
            }
        }
        __syncthreads();
    }
    float* X1 = g_hw + (size_t)b*CC*NN;
    #pragma unroll
    for (int ms = 0; ms < 2; ms++) {
        #pragma unroll
        for (int ns = 0; ns < 4; ns++) {
            int m = m0 + wm*32 + ms*16 + g;
            int n = n0 + wn*32 + ns*8 + tig*2;
            X1[(size_t)m*NN + n]       = acc[ms][ns][0];
            X1[(size_t)m*NN + n + 1]   = acc[ms][ns][1];
            X1[(size_t)(m+8)*NN + n]     = acc[ms][ns][2];
            X1[(size_t)(m+8)*NN + n + 1] = acc[ms][ns][3];
        }
    }
}

// -------- K5b: conv (fp32 exact) + spectral partial + bias + gelu --------
__global__ void k_conv(const float* __restrict__ convw, int l, int cur) {
    __shared__ float sA1[16][65];
    __shared__ float sB1[16][64];
    int b  = blockIdx.z;
    int m0 = blockIdx.y * 64;
    int n0 = blockIdx.x * 64;
    int tid = threadIdx.x;
    int tx = tid & 15, ty = tid >> 4;
    float acc[4][4] = {};
    int alr = tid & 15, alm = tid >> 4;
    int blr = tid >> 6, bln = tid & 63;
    const float* Wv = convw + (size_t)l*CC*CC + (size_t)m0*CC;
    const float* H  = g_h[cur] + (size_t)b*CC*NN;
    for (int r0 = 0; r0 < CC; r0 += 16) {
        #pragma unroll
        for (int i = 0; i < 4; i++) {
            int m = alm + 16*i;
            sA1[alr][m] = Wv[(size_t)m*CC + r0 + alr];
        }
        #pragma unroll
        for (int i = 0; i < 4; i++) {
            int r = blr + 4*i;
            sB1[r][bln] = H[(size_t)(r0 + r)*NN + n0 + bln];
        }
        __syncthreads();
        #pragma unroll
        for (int r = 0; r < 16; r++) {
            float a1[4], b1[4];
            #pragma unroll
            for (int i = 0; i < 4; i++) a1[i] = sA1[r][ty+16*i];
            #pragma unroll
            for (int j = 0; j < 4; j++) b1[j] = sB1[r][tx+16*j];
            #pragma unroll
            for (int i = 0; i < 4; i++)
                #pragma unroll
                for (int j = 0; j < 4; j++)
                    acc[i][j] += a1[i]*b1[j];
        }
        __syncthreads();
    }
    int nxt = cur ^ 1;
    const float* X1 = g_hw + (size_t)b*CC*NN;
    #pragma unroll
    for (int i = 0; i < 4; i++) {
        int m = m0 + ty + 16*i;
        float bias = g_f0h[b*CC + m];
        #pragma unroll
        for (int j = 0; j < 4; j++) {
            int n = n0 + tx + 16*j;
            float v = acc[i][j] + bias + X1[(size_t)m*NN + n];
            if (l < LL - 1) v = gelu_exact(v);
            g_h[nxt][((size_t)b*CC + m)*NN + n] = v;
        }
    }
}

// -------- K6: head --------
__global__ void k_head(const float* __restrict__ w1, const float* __restrict__ b1,
                       const float* __restrict__ w2, const float* __restrict__ b2,
                       float* __restrict__ out, int cur) {
    __shared__ float sh[CC][32];
    __shared__ float red[CC][33];
    int b  = blockIdx.y;
    int n0 = blockIdx.x * 32;
    int f = threadIdx.x;  // 0..127
    const float* H = g_h[cur] + (size_t)b*CC*NN + n0;
    #pragma unroll 4
    for (int c4 = 0; c4 < CC; c4 += 4) {
        int row = c4 + (f >> 5);
        int col = f & 31;
        sh[row][col] = H[(size_t)row*NN + col];
    }
    __syncthreads();
    float acc[32];
    float bv = b1[f];
    #pragma unroll
    for (int j = 0; j < 32; j++) acc[j] = bv;
    for (int c = 0; c < CC; c++) {
        float w = __ldg(&w1[(size_t)c*FCD + f]);
        #pragma unroll
        for (int j = 0; j < 32; j++) acc[j] += sh[c][j] * w;
    }
    float w2f = __ldg(&w2[f]);
    #pragma unroll
    for (int j = 0; j < 32; j++)
        red[f][j] = gelu_exact(acc[j]) * w2f;
    __syncthreads();
    if (f < 32) {
        float s = b2[0];
        #pragma unroll 8
        for (int q = 0; q < CC; q++) s += red[q][f];
        out[(size_t)b*NN + n0 + f] = s;
    }
}

// -------- launch --------
extern "C" void kernel_launch(void* const* d_in, const int* in_sizes, int n_in,
                              void* d_out, int out_size) {
    (void)in_sizes; (void)n_in; (void)out_size;
    const float* x     = (const float*)d_in[0];
    const float* xf    = (const float*)d_in[1];
    const int*   ind   = (const int*)  d_in[2];
    const float* modes = (const float*)d_in[3];
    const float* fc0_w = (const float*)d_in[4];
    const float* fc0_b = (const float*)d_in[5];
    const float* wc    = (const float*)d_in[6];
    const float* ws    = (const float*)d_in[7];
    const float* w0    = (const float*)d_in[8];
    const float* convw = (const float*)d_in[9];
    const float* convb = (const float*)d_in[10];
    const float* fc1_w = (const float*)d_in[11];
    const float* fc1_b = (const float*)d_in[12];
    const float* fc2_w = (const float*)d_in[13];
    const float* fc2_b = (const float*)d_in[14];
    float* out = (float*)d_out;

    k_basis<<<(BB*KK*NN + 255)/256, 256>>>(xf, ind, modes);

    dim3 g2(NN/256, CC, BB);
    k_fc0<<<g2, 256>>>(x, fc0_w, fc0_b);

    // forward spectral transform is loop-invariant: once from h0
    k_x0h<<<BB*CC, 256>>>();
    dim3 g3(KK/64, CC/32, BB);
    k_fwd_tc<<<g3, 256>>>();

    int cur = 0;
    for (int l = 0; l < LL; l++) {
        dim3 g4(CC, KK/128);
        k_mix<<<g4, 128>>>(wc, ws, l);
        k_f0h<<<1, BB*CC>>>(w0, convb, l);
        dim3 g5a(NN/128, CC/64, BB);
        k_inv_spec<<<g5a, 256>>>();
        dim3 g5b(NN/64, CC/64, BB);
        k_conv<<<g5b, 256>>>(convw, l, cur);
        cur ^= 1;
    }

    dim3 g6(NN/32, BB);
    k_head<<<g6, 128>>>(fc1_w, fc1_b, fc2_w, fc2_b, out, cur);
}

// round 5
// speedup vs baseline: 3.1916x; 1.8231x over previous
#include <cuda_runtime.h>
#include <math.h>
#include <stdint.h>

#define BB 4
#define NN 4096
#define NFF 8192
#define KK 512
#define CC 128
#define LL 4
#define INDIM 3
#define FCD 128
#define FWD_S 4   // split-N factor for forward GEMM

// -------- scratch (device globals) --------
__device__ float g_Bc[BB*KK*NN];           // cos basis (32 MB)
__device__ float g_Bs[BB*KK*NN];           // sin basis (32 MB)
__device__ float g_wqn[BB*NN];
__device__ float g_h[2][BB*CC*NN];         // ping-pong hidden state
__device__ float g_hw[BB*CC*NN];           // h0 * wqn
__device__ float g_xch[BB*CC*KK];
__device__ float g_xsp[BB*CC*KK];
__device__ float g_pc[FWD_S][BB*CC*KK];    // forward partials
__device__ float g_ps[FWD_S][BB*CC*KK];
__device__ float g_fA[LL][BB*CC*KK];       //  2*fch/nf  per layer
__device__ float g_fB[LL][BB*CC*KK];       // -2*fsh/nf  per layer
__device__ float g_x1[LL][BB*CC*NN];       // spectral inverse per layer (32 MB)
__device__ float g_x0h[BB*CC];
__device__ float g_f0h[LL][BB*CC];

__device__ __forceinline__ float gelu_exact(float v) {
    return 0.5f * v * (1.0f + erff(v * 0.7071067811865476f));
}
__device__ __forceinline__ float tf32r(float x) {
    float r;
    asm("cvt.rna.tf32.f32 %0, %1;" : "=f"(r) : "f"(x));
    return r;
}
__device__ __forceinline__ void split_tf32(float v, float& hi, float& lo) {
    hi = tf32r(v);
    lo = tf32r(v - hi);
}
// tf32 mma: D(16x8) += A(16x8) * B(8x8), fp32 accum
__device__ __forceinline__ void mma_tf32(float (&d)[4], const uint32_t (&a)[4],
                                         const uint32_t (&b)[2]) {
    asm volatile(
        "mma.sync.aligned.m16n8k8.row.col.f32.tf32.tf32.f32 "
        "{%0,%1,%2,%3}, {%4,%5,%6,%7}, {%8,%9}, {%0,%1,%2,%3};"
        : "+f"(d[0]), "+f"(d[1]), "+f"(d[2]), "+f"(d[3])
        : "r"(a[0]), "r"(a[1]), "r"(a[2]), "r"(a[3]), "r"(b[0]), "r"(b[1]));
}

// -------- K1: basis precompute --------
__global__ void k_basis(const float* __restrict__ xf, const int* __restrict__ ind,
                        const float* __restrict__ modes) {
    int idx = blockIdx.x * blockDim.x + threadIdx.x;
    if (idx >= BB*KK*NN) return;
    int n = idx & (NN - 1);
    int k = (idx >> 12) & (KK - 1);
    int b = idx >> 21;
    int f = __ldg(&ind[n]);
    const float* xfp = xf + ((size_t)b * NFF + f) * 4;
    float gx = __ldg(&xfp[0]);
    float gy = __ldg(&xfp[1]);
    float wq = __ldg(&xfp[2]);
    float mx = __ldg(&modes[2*k]);
    float my = __ldg(&modes[2*k+1]);
    float t = gx * mx + gy * my;
    float s, c;
    __sincosf(t, &s, &c);
    g_Bc[idx] = c;
    g_Bs[idx] = s;
    if (k == 0) g_wqn[b*NN + n] = wq * (float)NN;
}

// -------- K2: fc0 --------
__global__ void k_fc0(const float* __restrict__ x, const float* __restrict__ w,
                      const float* __restrict__ bias) {
    int n = blockIdx.x * blockDim.x + threadIdx.x;
    int c = blockIdx.y;
    int b = blockIdx.z;
    const float* xp = x + ((size_t)b * NN + n) * INDIM;
    float acc = bias[c]
              + xp[0] * w[0*CC + c]
              + xp[1] * w[1*CC + c]
              + xp[2] * w[2*CC + c];
    size_t o = ((size_t)b*CC + c) * NN + n;
    g_h[0][o] = acc;
    g_hw[o]   = acc * g_wqn[b*NN + n];
}

// -------- K2b: x0h reduce (once) --------
__global__ void k_x0h() {
    int bc = blockIdx.x;
    const float* p = g_hw + (size_t)bc * NN;
    float acc = 0.f;
    for (int n = threadIdx.x; n < NN; n += 256) acc += p[n];
    __shared__ float red[256];
    red[threadIdx.x] = acc;
    __syncthreads();
    for (int s = 128; s > 0; s >>= 1) {
        if (threadIdx.x < s) red[threadIdx.x] += red[threadIdx.x + s];
        __syncthreads();
    }
    if (threadIdx.x == 0) g_x0h[bc] = red[0];
}

// -------- K3: forward dual GEMM, tf32 TC, split-N partials --------
// partial[s]: xch/xsp[b,c,ko] = sum_{n in chunk s} hw[b,c,n] * Bc/Bs[b,ko,n]
__global__ void k_fwd_tc() {
    __shared__ float As[32][36];
    __shared__ float Bsm[2][64][36];
    int z   = blockIdx.z;
    int b   = z >> 2;
    int s   = z & 3;
    int m0  = blockIdx.y * 32;
    int ko0 = blockIdx.x * 64;
    int tid = threadIdx.x;
    int lane = tid & 31, wid = tid >> 5;
    int wm = wid >> 2, wn = wid & 3;
    int g = lane >> 2, tig = lane & 3;
    float acc[2][2][4] = {};
    const float* A  = g_hw + ((size_t)b*CC + m0) * NN + s * (NN/FWD_S);
    const float* Bc = g_Bc + ((size_t)b*KK + ko0) * NN + s * (NN/FWD_S);
    const float* Bs = g_Bs + ((size_t)b*KK + ko0) * NN + s * (NN/FWD_S);
    int arow = tid >> 3, ac4 = (tid & 7) * 4;
    for (int r0 = 0; r0 < NN/FWD_S; r0 += 32) {
        *(float4*)&As[arow][ac4] = *(const float4*)&A[(size_t)arow*NN + r0 + ac4];
        #pragma unroll
        for (int t = 0; t < 2; t++) {
            int idx = tid + t*256;
            int brow = idx >> 3, bc4 = (idx & 7) * 4;
            *(float4*)&Bsm[0][brow][bc4] = *(const float4*)&Bc[(size_t)brow*NN + r0 + bc4];
            *(float4*)&Bsm[1][brow][bc4] = *(const float4*)&Bs[(size_t)brow*NN + r0 + bc4];
        }
        __syncthreads();
        #pragma unroll
        for (int kk = 0; kk < 32; kk += 8) {
            uint32_t af[4];
            int m = wm * 16;
            af[0] = __float_as_uint(As[m+g  ][kk+tig  ]);
            af[1] = __float_as_uint(As[m+g+8][kk+tig  ]);
            af[2] = __float_as_uint(As[m+g  ][kk+tig+4]);
            af[3] = __float_as_uint(As[m+g+8][kk+tig+4]);
            #pragma unroll
            for (int p = 0; p < 2; p++) {
                #pragma unroll
                for (int ns = 0; ns < 2; ns++) {
                    int n = wn * 16 + ns * 8;
                    uint32_t bf[2];
                    bf[0] = __float_as_uint(Bsm[p][n+g][kk+tig  ]);
                    bf[1] = __float_as_uint(Bsm[p][n+g][kk+tig+4]);
                    mma_tf32(acc[p][ns], af, bf);
                }
            }
        }
        __syncthreads();
    }
    #pragma unroll
    for (int ns = 0; ns < 2; ns++) {
        int m = m0 + wm*16 + g;
        int k = ko0 + wn*16 + ns*8 + tig*2;
        size_t o0 = ((size_t)b*CC + m)*KK + k;
        size_t o1 = ((size_t)b*CC + m + 8)*KK + k;
        g_pc[s][o0]   = acc[0][ns][0];
        g_pc[s][o0+1] = acc[0][ns][1];
        g_pc[s][o1]   = acc[0][ns][2];
        g_pc[s][o1+1] = acc[0][ns][3];
        g_ps[s][o0]   = acc[1][ns][0];
        g_ps[s][o0+1] = acc[1][ns][1];
        g_ps[s][o1]   = acc[1][ns][2];
        g_ps[s][o1+1] = acc[1][ns][3];
    }
}

__global__ void k_fwd_red() {
    int i = blockIdx.x * 256 + threadIdx.x;
    float c = (g_pc[0][i] + g_pc[1][i]) + (g_pc[2][i] + g_pc[3][i]);
    float s = (g_ps[0][i] + g_ps[1][i]) + (g_ps[2][i] + g_ps[3][i]);
    g_xch[i] = c;
    g_xsp[i] = s;
}

// -------- K4: mode mix, ALL layers batched --------
__global__ void k_mix_all(const float* __restrict__ wc, const float* __restrict__ ws) {
    int o = blockIdx.x;                      // 0..127
    int k = blockIdx.y * 128 + threadIdx.x;  // 0..511
    int l = blockIdx.z;                      // 0..3
    const float inv_nf = 1.0f / (float)NFF;
    float accc[BB] = {0.f,0.f,0.f,0.f};
    float accs[BB] = {0.f,0.f,0.f,0.f};
    const float* wcp = wc + (((size_t)l*CC)*CC + o)*KK + k;
    const float* wsp = ws + (((size_t)l*CC)*CC + o)*KK + k;
    #pragma unroll 2
    for (int i = 0; i < CC; i++) {
        float wcv = __ldg(&wcp[(size_t)i*CC*KK]);
        float wsv = __ldg(&wsp[(size_t)i*CC*KK]);
        #pragma unroll
        for (int b = 0; b < BB; b++) {
            float xc = g_xch[((size_t)b*CC + i)*KK + k];
            float xs = g_xsp[((size_t)b*CC + i)*KK + k];
            accc[b] += xc*wcv + xs*wsv;
            accs[b] += xc*wsv - xs*wcv;
        }
    }
    #pragma unroll
    for (int b = 0; b < BB; b++) {
        g_fA[l][((size_t)b*CC + o)*KK + k] =  2.0f * inv_nf * accc[b];
        g_fB[l][((size_t)b*CC + o)*KK + k] = -2.0f * inv_nf * accs[b];
    }
}

// -------- K4b: f0h, all layers --------
__global__ void k_f0h_all(const float* __restrict__ w0, const float* __restrict__ convb) {
    int l = blockIdx.x;
    int t = threadIdx.x;
    int b = t >> 7, o = t & 127;
    float acc = 0.f;
    #pragma unroll 4
    for (int i = 0; i < CC; i++)
        acc += g_x0h[b*CC + i] * __ldg(&w0[((size_t)l*CC + i)*CC + o]);
    g_f0h[l][t] = acc * (1.0f / (float)NFF) + convb[l*CC + o];
}

// -------- K5a: inverse spectral GEMM, all layers batched, tf32 TC --------
__global__ void k_inv_spec_all() {
    __shared__ float As[2][64][20];
    __shared__ float Bsm[2][16][132];
    int z  = blockIdx.z;
    int b  = z & (BB-1);
    int l  = z >> 2;
    int m0 = blockIdx.y * 64;
    int n0 = blockIdx.x * 128;
    int tid = threadIdx.x;
    int lane = tid & 31, wid = tid >> 5;
    int wm = wid >> 2, wn = wid & 3;
    int g = lane >> 2, tig = lane & 3;
    float acc[2][4][4] = {};
    const float* fA = g_fA[l] + ((size_t)b*CC + m0)*KK;
    const float* fB = g_fB[l] + ((size_t)b*CC + m0)*KK;
    const float* Bc = g_Bc + (size_t)b*KK*NN;
    const float* Bs = g_Bs + (size_t)b*KK*NN;
    int arow = tid >> 2, ac4 = (tid & 3) * 4;
    for (int r0 = 0; r0 < KK; r0 += 16) {
        *(float4*)&As[0][arow][ac4] = *(const float4*)&fA[(size_t)arow*KK + r0 + ac4];
        *(float4*)&As[1][arow][ac4] = *(const float4*)&fB[(size_t)arow*KK + r0 + ac4];
        #pragma unroll
        for (int t = 0; t < 2; t++) {
            int idx = tid + t*256;
            int brow = idx >> 5, bc4 = (idx & 31) * 4;
            *(float4*)&Bsm[0][brow][bc4] = *(const float4*)&Bc[(size_t)(r0+brow)*NN + n0 + bc4];
            *(float4*)&Bsm[1][brow][bc4] = *(const float4*)&Bs[(size_t)(r0+brow)*NN + n0 + bc4];
        }
        __syncthreads();
        #pragma unroll
        for (int kk = 0; kk < 16; kk += 8) {
            #pragma unroll
            for (int p = 0; p < 2; p++) {
                uint32_t af[2][4];
                #pragma unroll
                for (int ms = 0; ms < 2; ms++) {
                    int m = wm*32 + ms*16;
                    af[ms][0] = __float_as_uint(As[p][m+g  ][kk+tig  ]);
                    af[ms][1] = __float_as_uint(As[p][m+g+8][kk+tig  ]);
                    af[ms][2] = __float_as_uint(As[p][m+g  ][kk+tig+4]);
                    af[ms][3] = __float_as_uint(As[p][m+g+8][kk+tig+4]);
                }
                #pragma unroll
                for (int ns = 0; ns < 4; ns++) {
                    int n = wn*32 + ns*8;
                    uint32_t bf[2];
                    bf[0] = __float_as_uint(Bsm[p][kk+tig  ][n+g]);
                    bf[1] = __float_as_uint(Bsm[p][kk+tig+4][n+g]);
                    #pragma unroll
                    for (int ms = 0; ms < 2; ms++)
                        mma_tf32(acc[ms][ns], af[ms], bf);
                }
            }
        }
        __syncthreads();
    }
    float* X1 = g_x1[l] + (size_t)b*CC*NN;
    #pragma unroll
    for (int ms = 0; ms < 2; ms++) {
        #pragma unroll
        for (int ns = 0; ns < 4; ns++) {
            int m = m0 + wm*32 + ms*16 + g;
            int n = n0 + wn*32 + ns*8 + tig*2;
            X1[(size_t)m*NN + n]         = acc[ms][ns][0];
            X1[(size_t)m*NN + n + 1]     = acc[ms][ns][1];
            X1[(size_t)(m+8)*NN + n]     = acc[ms][ns][2];
            X1[(size_t)(m+8)*NN + n + 1] = acc[ms][ns][3];
        }
    }
}

// -------- K5b: conv via 3xTF32 tensor cores + epilogue --------
// x2[b,o,n] = sum_i convw[l,o,i] * h[b,i,n];  h' = gelu(x2 + x1 + f0h')
__global__ void k_conv_tc(const float* __restrict__ convw, int l, int cur) {
    __shared__ float Ah[64][20], Al[64][20];
    __shared__ float Bh[16][132], Bl[16][132];
    int b  = blockIdx.z;
    int m0 = blockIdx.y * 64;
    int n0 = blockIdx.x * 128;
    int tid = threadIdx.x;
    int lane = tid & 31, wid = tid >> 5;
    int wm = wid >> 2, wn = wid & 3;
    int g = lane >> 2, tig = lane & 3;
    float acc[2][4][4] = {};
    const float* W = convw + (size_t)l*CC*CC + (size_t)m0*CC;
    const float* H = g_h[cur] + (size_t)b*CC*NN;
    int arow = tid >> 2, ac4 = (tid & 3) * 4;
    for (int r0 = 0; r0 < CC; r0 += 16) {
        float4 va = *(const float4*)&W[(size_t)arow*CC + r0 + ac4];
        float h0,l0,h1,l1,h2,l2,h3,l3;
        split_tf32(va.x, h0, l0); split_tf32(va.y, h1, l1);
        split_tf32(va.z, h2, l2); split_tf32(va.w, h3, l3);
        Ah[arow][ac4] = h0; Ah[arow][ac4+1] = h1; Ah[arow][ac4+2] = h2; Ah[arow][ac4+3] = h3;
        Al[arow][ac4] = l0; Al[arow][ac4+1] = l1; Al[arow][ac4+2] = l2; Al[arow][ac4+3] = l3;
        #pragma unroll
        for (int t = 0; t < 2; t++) {
            int idx = tid + t*256;
            int brow = idx >> 5, bc4 = (idx & 31) * 4;
            float4 vb = *(const float4*)&H[(size_t)(r0+brow)*NN + n0 + bc4];
            float bh0,bl0,bh1,bl1,bh2,bl2,bh3,bl3;
            split_tf32(vb.x, bh0, bl0); split_tf32(vb.y, bh1, bl1);
            split_tf32(vb.z, bh2, bl2); split_tf32(vb.w, bh3, bl3);
            Bh[brow][bc4] = bh0; Bh[brow][bc4+1] = bh1; Bh[brow][bc4+2] = bh2; Bh[brow][bc4+3] = bh3;
            Bl[brow][bc4] = bl0; Bl[brow][bc4+1] = bl1; Bl[brow][bc4+2] = bl2; Bl[brow][bc4+3] = bl3;
        }
        __syncthreads();
        #pragma unroll
        for (int kk = 0; kk < 16; kk += 8) {
            uint32_t afh[2][4], afl[2][4];
            #pragma unroll
            for (int ms = 0; ms < 2; ms++) {
                int m = wm*32 + ms*16;
                afh[ms][0] = __float_as_uint(Ah[m+g  ][kk+tig  ]);
                afh[ms][1] = __float_as_uint(Ah[m+g+8][kk+tig  ]);
                afh[ms][2] = __float_as_uint(Ah[m+g  ][kk+tig+4]);
                afh[ms][3] = __float_as_uint(Ah[m+g+8][kk+tig+4]);
                afl[ms][0] = __float_as_uint(Al[m+g  ][kk+tig  ]);
                afl[ms][1] = __float_as_uint(Al[m+g+8][kk+tig  ]);
                afl[ms][2] = __float_as_uint(Al[m+g  ][kk+tig+4]);
                afl[ms][3] = __float_as_uint(Al[m+g+8][kk+tig+4]);
            }
            #pragma unroll
            for (int ns = 0; ns < 4; ns++) {
                int n = wn*32 + ns*8;
                uint32_t bfh[2], bfl[2];
                bfh[0] = __float_as_uint(Bh[kk+tig  ][n+g]);
                bfh[1] = __float_as_uint(Bh[kk+tig+4][n+g]);
                bfl[0] = __float_as_uint(Bl[kk+tig  ][n+g]);
                bfl[1] = __float_as_uint(Bl[kk+tig+4][n+g]);
                #pragma unroll
                for (int ms = 0; ms < 2; ms++) {
                    mma_tf32(acc[ms][ns], afh[ms], bfh);
                    mma_tf32(acc[ms][ns], afh[ms], bfl);
                    mma_tf32(acc[ms][ns], afl[ms], bfh);
                }
            }
        }
        __syncthreads();
    }
    int nxt = cur ^ 1;
    const float* X1 = g_x1[l] + (size_t)b*CC*NN;
    float* Hn = g_h[nxt] + (size_t)b*CC*NN;
    #pragma unroll
    for (int ms = 0; ms < 2; ms++) {
        #pragma unroll
        for (int ns = 0; ns < 4; ns++) {
            int m = m0 + wm*32 + ms*16 + g;
            int n = n0 + wn*32 + ns*8 + tig*2;
            float bias0 = g_f0h[l][b*CC + m];
            float bias1 = g_f0h[l][b*CC + m + 8];
            float v0 = acc[ms][ns][0] + bias0 + X1[(size_t)m*NN + n];
            float v1 = acc[ms][ns][1] + bias0 + X1[(size_t)m*NN + n + 1];
            float v2 = acc[ms][ns][2] + bias1 + X1[(size_t)(m+8)*NN + n];
            float v3 = acc[ms][ns][3] + bias1 + X1[(size_t)(m+8)*NN + n + 1];
            if (l < LL - 1) {
                v0 = gelu_exact(v0); v1 = gelu_exact(v1);
                v2 = gelu_exact(v2); v3 = gelu_exact(v3);
            }
            Hn[(size_t)m*NN + n]         = v0;
            Hn[(size_t)m*NN + n + 1]     = v1;
            Hn[(size_t)(m+8)*NN + n]     = v2;
            Hn[(size_t)(m+8)*NN + n + 1] = v3;
        }
    }
}

// -------- K6: head --------
__global__ void k_head(const float* __restrict__ w1, const float* __restrict__ b1,
                       const float* __restrict__ w2, const float* __restrict__ b2,
                       float* __restrict__ out, int cur) {
    __shared__ float sh[CC][32];
    __shared__ float red[CC][33];
    int b  = blockIdx.y;
    int n0 = blockIdx.x * 32;
    int f = threadIdx.x;  // 0..127
    const float* H = g_h[cur] + (size_t)b*CC*NN + n0;
    #pragma unroll 4
    for (int c4 = 0; c4 < CC; c4 += 4) {
        int row = c4 + (f >> 5);
        int col = f & 31;
        sh[row][col] = H[(size_t)row*NN + col];
    }
    __syncthreads();
    float acc[32];
    float bv = b1[f];
    #pragma unroll
    for (int j = 0; j < 32; j++) acc[j] = bv;
    for (int c = 0; c < CC; c++) {
        float w = __ldg(&w1[(size_t)c*FCD + f]);
        #pragma unroll
        for (int j = 0; j < 32; j++) acc[j] += sh[c][j] * w;
    }
    float w2f = __ldg(&w2[f]);
    #pragma unroll
    for (int j = 0; j < 32; j++)
        red[f][j] = gelu_exact(acc[j]) * w2f;
    __syncthreads();
    if (f < 32) {
        float s = b2[0];
        #pragma unroll 8
        for (int q = 0; q < CC; q++) s += red[q][f];
        out[(size_t)b*NN + n0 + f] = s;
    }
}

// -------- launch --------
extern "C" void kernel_launch(void* const* d_in, const int* in_sizes, int n_in,
                              void* d_out, int out_size) {
    (void)in_sizes; (void)n_in; (void)out_size;
    const float* x     = (const float*)d_in[0];
    const float* xf    = (const float*)d_in[1];
    const int*   ind   = (const int*)  d_in[2];
    const float* modes = (const float*)d_in[3];
    const float* fc0_w = (const float*)d_in[4];
    const float* fc0_b = (const float*)d_in[5];
    const float* wc    = (const float*)d_in[6];
    const float* ws    = (const float*)d_in[7];
    const float* w0    = (const float*)d_in[8];
    const float* convw = (const float*)d_in[9];
    const float* convb = (const float*)d_in[10];
    const float* fc1_w = (const float*)d_in[11];
    const float* fc1_b = (const float*)d_in[12];
    const float* fc2_w = (const float*)d_in[13];
    const float* fc2_b = (const float*)d_in[14];
    float* out = (float*)d_out;

    k_basis<<<(BB*KK*NN + 255)/256, 256>>>(xf, ind, modes);

    dim3 g2(NN/256, CC, BB);
    k_fc0<<<g2, 256>>>(x, fc0_w, fc0_b);

    // forward spectral transform (loop-invariant): split-N + reduce
    k_x0h<<<BB*CC, 256>>>();
    dim3 g3(KK/64, CC/32, BB*FWD_S);
    k_fwd_tc<<<g3, 256>>>();
    k_fwd_red<<<BB*CC*KK/256, 256>>>();

    // all layers' spectral work is independent of the h-chain: batch it
    dim3 g4(CC, KK/128, LL);
    k_mix_all<<<g4, 128>>>(wc, ws);
    k_f0h_all<<<LL, BB*CC>>>(w0, convb);
    dim3 g5(NN/128, CC/64, BB*LL);
    k_inv_spec_all<<<g5, 256>>>();

    // sequential conv chain (3xTF32 tensor cores)
    int cur = 0;
    for (int l = 0; l < LL; l++) {
        dim3 g6(NN/128, CC/64, BB);
        k_conv_tc<<<g6, 256>>>(convw, l, cur);
        cur ^= 1;
    }

    dim3 g7(NN/32, BB);
    k_head<<<g7, 128>>>(fc1_w, fc1_b, fc2_w, fc2_b, out, cur);
}